// round 1
// baseline (speedup 1.0000x reference)
#include <cuda_runtime.h>
#include <cuda_bf16.h>
#include <math.h>

// Problem constants
#define B_  2
#define T_  2048
#define D_  2048
#define H_  16
#define DH_ 128
#define M_  4096            // B_*T_

// Scratch (allocation-free rule: __device__ globals)
__device__ float g_q[8388608];   // [M_, D_]
__device__ float g_k[8388608];
__device__ float g_v[8388608];
__device__ float g_o[8388608];

// ----------------------------------------------------------------------------
// SGEMM-NT + bias: C[m][n] = sum_k A[m][k]*B[n][k] + bias[n]
// A: [Md, Kd] row-major, B: [Nd, Kd] row-major.
// 128x128 tile, BK=16, 256 threads, 8x8 micro-tile.
// ----------------------------------------------------------------------------
#define GBM 128
#define GBN 128
#define GBK 16
#define GP  132   // padded stride for smem (k-major): As[k*GP + m]

__global__ __launch_bounds__(256) void sgemm_nt_bias(
    const float* __restrict__ A, const float* __restrict__ Bm,
    const float* __restrict__ bias, float* __restrict__ C,
    int Md, int Nd, int Kd)
{
    __shared__ float As[GBK * GP];
    __shared__ float Bs[GBK * GP];
    const int tid = threadIdx.x;
    const int bm = blockIdx.y * GBM;
    const int bn = blockIdx.x * GBN;
    const int tx = tid & 15;
    const int ty = tid >> 4;

    float acc[8][8];
#pragma unroll
    for (int i = 0; i < 8; i++)
#pragma unroll
        for (int j = 0; j < 8; j++) acc[i][j] = 0.f;

    for (int k0 = 0; k0 < Kd; k0 += GBK) {
#pragma unroll
        for (int l = 0; l < 2; l++) {
            int idx = tid + l * 256;        // 0..511
            int r = idx >> 2;               // row 0..127
            int c = (idx & 3) << 2;         // col 0,4,8,12
            float4 va = *(const float4*)(A + (size_t)(bm + r) * Kd + k0 + c);
            As[(c + 0) * GP + r] = va.x;
            As[(c + 1) * GP + r] = va.y;
            As[(c + 2) * GP + r] = va.z;
            As[(c + 3) * GP + r] = va.w;
            float4 vb = *(const float4*)(Bm + (size_t)(bn + r) * Kd + k0 + c);
            Bs[(c + 0) * GP + r] = vb.x;
            Bs[(c + 1) * GP + r] = vb.y;
            Bs[(c + 2) * GP + r] = vb.z;
            Bs[(c + 3) * GP + r] = vb.w;
        }
        __syncthreads();
#pragma unroll
        for (int kk = 0; kk < GBK; kk++) {
            float av[8], bv[8];
            *(float4*)&av[0] = *(const float4*)&As[kk * GP + ty * 8];
            *(float4*)&av[4] = *(const float4*)&As[kk * GP + ty * 8 + 4];
            *(float4*)&bv[0] = *(const float4*)&Bs[kk * GP + tx * 8];
            *(float4*)&bv[4] = *(const float4*)&Bs[kk * GP + tx * 8 + 4];
#pragma unroll
            for (int i = 0; i < 8; i++)
#pragma unroll
                for (int j = 0; j < 8; j++)
                    acc[i][j] += av[i] * bv[j];
        }
        __syncthreads();
    }

    float bb[8];
#pragma unroll
    for (int j = 0; j < 8; j++) bb[j] = bias[bn + tx * 8 + j];
#pragma unroll
    for (int i = 0; i < 8; i++) {
        float* Cr = C + (size_t)(bm + ty * 8 + i) * Nd + bn + tx * 8;
        float4 o0 = make_float4(acc[i][0] + bb[0], acc[i][1] + bb[1],
                                acc[i][2] + bb[2], acc[i][3] + bb[3]);
        float4 o1 = make_float4(acc[i][4] + bb[4], acc[i][5] + bb[5],
                                acc[i][6] + bb[6], acc[i][7] + bb[7]);
        *(float4*)Cr = o0;
        *(float4*)(Cr + 4) = o1;
    }
}

// ----------------------------------------------------------------------------
// Fused RMSNorm (over full D) + interleaved RoPE, in place. One block per row.
// out[2i]   = e*cos[2i]   - o*sin[2i]
// out[2i+1] = o*cos[2i+1] + e*sin[2i+1]   with e,o = normalized even/odd.
// ----------------------------------------------------------------------------
__global__ __launch_bounds__(256) void rmsnorm_rope(
    float* __restrict__ h, const float* __restrict__ w,
    const float* __restrict__ cosb, const float* __restrict__ sinb)
{
    const int row = blockIdx.x;
    const int t = row & (T_ - 1);
    float* hr = h + (size_t)row * D_;

    float ss = 0.f;
    for (int i = threadIdx.x; i < D_; i += 256) { float v = hr[i]; ss += v * v; }
#pragma unroll
    for (int o = 16; o > 0; o >>= 1) ss += __shfl_xor_sync(0xffffffffu, ss, o);
    __shared__ float red[8];
    __shared__ float s_inv;
    if ((threadIdx.x & 31) == 0) red[threadIdx.x >> 5] = ss;
    __syncthreads();
    if (threadIdx.x == 0) {
        float s = 0.f;
        for (int i = 0; i < 8; i++) s += red[i];
        s_inv = rsqrtf(s * (1.0f / D_) + 1e-6f);
    }
    __syncthreads();
    const float inv = s_inv;
    const float* ct = cosb + (size_t)t * D_;
    const float* st = sinb + (size_t)t * D_;
    for (int i = threadIdx.x; i < D_ / 2; i += 256) {
        int i2 = i * 2;
        float e = hr[i2] * inv * w[i2];
        float o = hr[i2 + 1] * inv * w[i2 + 1];
        hr[i2]     = e * ct[i2]     - o * st[i2];
        hr[i2 + 1] = o * ct[i2 + 1] + e * st[i2 + 1];
    }
}

// ----------------------------------------------------------------------------
// fp32 flash attention (non-causal). BM=BN=64, Dh=128.
// grid = (T/64, H, B), 256 threads. Dynamic smem ~113.5 KB.
// ----------------------------------------------------------------------------
__global__ __launch_bounds__(256) void flash_attn(
    const float* __restrict__ Q, const float* __restrict__ K,
    const float* __restrict__ V, float* __restrict__ O)
{
    constexpr int BM = 64, BN = 64;
    constexpr int SKP = 129;   // K tile row stride (conflict pad)
    constexpr int SVP = 132;   // V tile row stride (16B-aligned pad)
    constexpr int SSP = 65;    // S tile row stride
    extern __shared__ float sm[];
    float* sQ = sm;                    // 64*128
    float* sK = sQ + BM * DH_;         // 64*129
    float* sV = sK + BN * SKP;         // 64*132
    float* sS = sV + BN * SVP;         // 64*65
    __shared__ float m_s[BM], l_s[BM], al_s[BM];

    const int tid = threadIdx.x;
    const int b = blockIdx.z, h = blockIdx.y;
    const int q0 = blockIdx.x * BM;
    const int tx = tid & 15, ty = tid >> 4;

    const float* Qb = Q + ((size_t)b * T_ + q0) * D_ + h * DH_;
    for (int i = tid; i < BM * (DH_ / 4); i += 256) {
        int r = i >> 5, c = (i & 31) << 2;
        *(float4*)(sQ + r * DH_ + c) = *(const float4*)(Qb + (size_t)r * D_ + c);
    }
    if (tid < BM) { m_s[tid] = -1e30f; l_s[tid] = 0.f; }

    float acc[4][8];
#pragma unroll
    for (int i = 0; i < 4; i++)
#pragma unroll
        for (int j = 0; j < 8; j++) acc[i][j] = 0.f;
    __syncthreads();

    const float scale = 0.08838834764831845f;  // 1/sqrt(128)

    for (int kt = 0; kt < T_ / BN; kt++) {
        const float* Kb = K + ((size_t)b * T_ + kt * BN) * D_ + h * DH_;
        const float* Vb = V + ((size_t)b * T_ + kt * BN) * D_ + h * DH_;
        for (int i = tid; i < BN * (DH_ / 4); i += 256) {
            int r = i >> 5, c = (i & 31) << 2;
            float4 kv = *(const float4*)(Kb + (size_t)r * D_ + c);
            sK[r * SKP + c]     = kv.x;
            sK[r * SKP + c + 1] = kv.y;
            sK[r * SKP + c + 2] = kv.z;
            sK[r * SKP + c + 3] = kv.w;
            *(float4*)(sV + r * SVP + c) = *(const float4*)(Vb + (size_t)r * D_ + c);
        }
        __syncthreads();

        // S = scale * Q K^T  (thread: 4 rows x 4 cols of 64x64)
        float s4[4][4];
#pragma unroll
        for (int i = 0; i < 4; i++)
#pragma unroll
            for (int j = 0; j < 4; j++) s4[i][j] = 0.f;
#pragma unroll 4
        for (int d = 0; d < DH_; d++) {
            float a[4], bb[4];
#pragma unroll
            for (int i = 0; i < 4; i++) a[i] = sQ[(ty * 4 + i) * DH_ + d];
#pragma unroll
            for (int j = 0; j < 4; j++) bb[j] = sK[(tx * 4 + j) * SKP + d];
#pragma unroll
            for (int i = 0; i < 4; i++)
#pragma unroll
                for (int j = 0; j < 4; j++)
                    s4[i][j] += a[i] * bb[j];
        }
#pragma unroll
        for (int i = 0; i < 4; i++)
#pragma unroll
            for (int j = 0; j < 4; j++)
                sS[(ty * 4 + i) * SSP + tx * 4 + j] = s4[i][j] * scale;
        __syncthreads();

        // Online softmax: one thread per row
        if (tid < BM) {
            float* row = sS + tid * SSP;
            float mold = m_s[tid];
            float mx = mold;
            for (int j = 0; j < BN; j++) mx = fmaxf(mx, row[j]);
            float sum = 0.f;
            for (int j = 0; j < BN; j++) { float p = __expf(row[j] - mx); row[j] = p; sum += p; }
            float alpha = __expf(mold - mx);
            m_s[tid] = mx;
            l_s[tid] = l_s[tid] * alpha + sum;
            al_s[tid] = alpha;
        }
        __syncthreads();

        // Rescale accumulators + P@V  (thread: 4 rows x 8 cols of 64x128)
        float al[4];
#pragma unroll
        for (int i = 0; i < 4; i++) al[i] = al_s[ty * 4 + i];
#pragma unroll
        for (int i = 0; i < 4; i++)
#pragma unroll
            for (int j = 0; j < 8; j++) acc[i][j] *= al[i];
#pragma unroll 4
        for (int k = 0; k < BN; k++) {
            float p[4];
#pragma unroll
            for (int i = 0; i < 4; i++) p[i] = sS[(ty * 4 + i) * SSP + k];
            float v8[8];
            *(float4*)&v8[0] = *(const float4*)(sV + k * SVP + tx * 8);
            *(float4*)&v8[4] = *(const float4*)(sV + k * SVP + tx * 8 + 4);
#pragma unroll
            for (int i = 0; i < 4; i++)
#pragma unroll
                for (int j = 0; j < 8; j++)
                    acc[i][j] += p[i] * v8[j];
        }
        __syncthreads();
    }

    float* Ob = O + ((size_t)b * T_ + q0) * D_ + h * DH_;
#pragma unroll
    for (int i = 0; i < 4; i++) {
        float inv = 1.f / l_s[ty * 4 + i];
        float4 o0 = make_float4(acc[i][0] * inv, acc[i][1] * inv,
                                acc[i][2] * inv, acc[i][3] * inv);
        float4 o1 = make_float4(acc[i][4] * inv, acc[i][5] * inv,
                                acc[i][6] * inv, acc[i][7] * inv);
        float* dst = Ob + (size_t)(ty * 4 + i) * D_ + tx * 8;
        *(float4*)dst = o0;
        *(float4*)(dst + 4) = o1;
    }
}

// ----------------------------------------------------------------------------
// Launch
// ----------------------------------------------------------------------------
extern "C" void kernel_launch(void* const* d_in, const int* in_sizes, int n_in,
                              void* d_out, int out_size)
{
    const float* x    = (const float*)d_in[0];
    const float* cosb = (const float*)d_in[1];
    const float* sinb = (const float*)d_in[2];
    const float* Wq   = (const float*)d_in[3];
    const float* bq   = (const float*)d_in[4];
    const float* Wk   = (const float*)d_in[5];
    const float* bk   = (const float*)d_in[6];
    const float* Wv   = (const float*)d_in[7];
    const float* bv   = (const float*)d_in[8];
    const float* qnw  = (const float*)d_in[9];
    const float* knw  = (const float*)d_in[10];
    const float* Wo   = (const float*)d_in[11];
    const float* bo   = (const float*)d_in[12];
    float* out = (float*)d_out;

    float *qp, *kp, *vp, *op;
    cudaGetSymbolAddress((void**)&qp, g_q);
    cudaGetSymbolAddress((void**)&kp, g_k);
    cudaGetSymbolAddress((void**)&vp, g_v);
    cudaGetSymbolAddress((void**)&op, g_o);

    dim3 ggrid(D_ / GBN, M_ / GBM);  // (16, 32)
    sgemm_nt_bias<<<ggrid, 256>>>(x, Wq, bq, qp, M_, D_, D_);
    sgemm_nt_bias<<<ggrid, 256>>>(x, Wk, bk, kp, M_, D_, D_);
    sgemm_nt_bias<<<ggrid, 256>>>(x, Wv, bv, vp, M_, D_, D_);

    rmsnorm_rope<<<M_, 256>>>(qp, qnw, cosb, sinb);
    rmsnorm_rope<<<M_, 256>>>(kp, knw, cosb, sinb);

    const int flash_smem = (64 * 128 + 64 * 129 + 64 * 132 + 64 * 65) * 4;  // 116224 B
    cudaFuncSetAttribute(flash_attn, cudaFuncAttributeMaxDynamicSharedMemorySize, flash_smem);
    flash_attn<<<dim3(T_ / 64, H_, B_), 256, flash_smem>>>(qp, kp, vp, op);

    sgemm_nt_bias<<<ggrid, 256>>>(op, Wo, bo, out, M_, D_, D_);
}

// round 4
// speedup vs baseline: 1.5150x; 1.5150x over previous
#include <cuda_runtime.h>
#include <cuda_bf16.h>
#include <math.h>
#include <stdint.h>

// Problem constants
#define B_  2
#define T_  2048
#define D_  2048
#define H_  16
#define DH_ 128
#define M_  4096            // B_*T_

// ---------------- scratch (__device__ globals; no allocs allowed) ----------
__device__ __align__(256) float g_q[8388608];
__device__ __align__(256) float g_k[8388608];
__device__ __align__(256) float g_v[8388608];
__device__ __align__(256) float g_o[8388608];
__device__ __align__(256) __nv_bfloat16 g_xh[8388608], g_xl[8388608];
__device__ __align__(256) __nv_bfloat16 g_oh[8388608], g_ol[8388608];
__device__ __align__(256) __nv_bfloat16 g_wqh[4194304], g_wql[4194304];
__device__ __align__(256) __nv_bfloat16 g_wkh[4194304], g_wkl[4194304];
__device__ __align__(256) __nv_bfloat16 g_wvh[4194304], g_wvl[4194304];
__device__ __align__(256) __nv_bfloat16 g_woh[4194304], g_wol[4194304];

// ---------------- PTX helpers ----------------------------------------------
__device__ __forceinline__ uint32_t smem_u32(const void* p) {
    uint32_t a;
    asm("{ .reg .u64 t; cvta.to.shared.u64 t, %1; cvt.u32.u64 %0, t; }" : "=r"(a) : "l"(p));
    return a;
}
__device__ __forceinline__ void cpa16(uint32_t s, const void* g) {
    asm volatile("cp.async.cg.shared.global [%0], [%1], 16;" :: "r"(s), "l"(g));
}
__device__ __forceinline__ void ldx4(uint32_t* d, uint32_t addr) {
    asm volatile("ldmatrix.sync.aligned.m8n8.x4.shared.b16 {%0,%1,%2,%3}, [%4];"
                 : "=r"(d[0]), "=r"(d[1]), "=r"(d[2]), "=r"(d[3]) : "r"(addr));
}
__device__ __forceinline__ void ldx2(uint32_t* d, uint32_t addr) {
    asm volatile("ldmatrix.sync.aligned.m8n8.x2.shared.b16 {%0,%1}, [%2];"
                 : "=r"(d[0]), "=r"(d[1]) : "r"(addr));
}
__device__ __forceinline__ void mma_bf16(float* c, const uint32_t* a, const uint32_t* b) {
    asm volatile(
        "mma.sync.aligned.m16n8k16.row.col.f32.bf16.bf16.f32 "
        "{%0,%1,%2,%3}, {%4,%5,%6,%7}, {%8,%9}, {%0,%1,%2,%3};"
        : "+f"(c[0]), "+f"(c[1]), "+f"(c[2]), "+f"(c[3])
        : "r"(a[0]), "r"(a[1]), "r"(a[2]), "r"(a[3]), "r"(b[0]), "r"(b[1]));
}
// swizzle for 64-byte rows (8 rows / 512B period): XOR 16B-chunk bits with row bits
__device__ __forceinline__ uint32_t swz(uint32_t off) { return off ^ ((off >> 3) & 0x30); }

// ---------------------------------------------------------------------------
// mma.sync GEMM-NT with bf16 2-term split + fp32 accumulation.
// C[m][n] = sum_k (Ah+Al)[m][k]*(Bh+Bl)[n][k] + bias[n]   (Al*Bl dropped)
// BM=BN=128, BK=32, 256 threads (8 warps: 2m x 4n, warp tile 64x32), 3 stages.
// ---------------------------------------------------------------------------
#define STAGE_B 32768           // Ah 8K | Al 8K | Bh 8K | Bl 8K
#define GEMM_SMEM (3 * STAGE_B)

__global__ __launch_bounds__(256, 1) void gemm_mma_split(
    const __nv_bfloat16* __restrict__ Ah, const __nv_bfloat16* __restrict__ Al,
    const __nv_bfloat16* __restrict__ Bh, const __nv_bfloat16* __restrict__ Bl,
    const float* __restrict__ bias, float* __restrict__ C,
    int Md, int Nd, int Kd)
{
    extern __shared__ __align__(1024) unsigned char smem[];
    const int tid = threadIdx.x;
    const int wid = tid >> 5;
    const int lane = tid & 31;
    const int wm = wid >> 2;          // 0..1 -> m offset wm*64
    const int wn = wid & 3;           // 0..3 -> n offset wn*32
    const int bm = blockIdx.y * 128;
    const int bn = blockIdx.x * 128;
    const uint32_t sbase = smem_u32(smem);
    const int nchunk = Kd >> 5;       // 64

#define LOAD_STAGE(stage, k0)                                                   \
    {                                                                            \
        uint32_t sb = sbase + (stage) * STAGE_B;                                 \
        _Pragma("unroll")                                                        \
        for (int j = 0; j < 2; j++) {                                            \
            int idx = tid + j * 256;                                             \
            int r = idx >> 2, c = idx & 3;                                       \
            uint32_t so = swz((uint32_t)(r * 64 + c * 16));                      \
            size_t ga = (size_t)(bm + r) * Kd + (k0) + c * 8;                    \
            size_t gb = (size_t)(bn + r) * Kd + (k0) + c * 8;                    \
            cpa16(sb + so,         Ah + ga);                                     \
            cpa16(sb + 8192 + so,  Al + ga);                                     \
            cpa16(sb + 16384 + so, Bh + gb);                                     \
            cpa16(sb + 24576 + so, Bl + gb);                                     \
        }                                                                        \
        asm volatile("cp.async.commit_group;" ::: "memory");                     \
    }

    LOAD_STAGE(0, 0)
    LOAD_STAGE(1, 32)

    float acc[4][4][4];
#pragma unroll
    for (int i = 0; i < 4; i++)
#pragma unroll
        for (int j = 0; j < 4; j++)
#pragma unroll
            for (int l = 0; l < 4; l++) acc[i][j][l] = 0.f;

    const int arow = lane & 15;
    const int akh = lane >> 4;            // k-half for A ldmatrix
    const int bln = lane & 15;
    const int brow = bln & 7;
    const int bkh = (bln >> 3) & 1;

    for (int i = 0; i < nchunk; i++) {
        if (i + 2 < nchunk) {
            LOAD_STAGE((i + 2) % 3, (i + 2) * 32)
            asm volatile("cp.async.wait_group 2;" ::: "memory");
        } else if (i + 1 < nchunk) {
            asm volatile("cp.async.wait_group 1;" ::: "memory");
        } else {
            asm volatile("cp.async.wait_group 0;" ::: "memory");
        }
        __syncthreads();

        const uint32_t sb = sbase + (i % 3) * STAGE_B;
#pragma unroll
        for (int ks = 0; ks < 2; ks++) {
            uint32_t ah[4][4], al[4][4], bh[4][2], bl[4][2];
#pragma unroll
            for (int mi = 0; mi < 4; mi++) {
                uint32_t off = swz((uint32_t)((wm * 64 + mi * 16 + arow) * 64 + ks * 32 + akh * 16));
                ldx4(ah[mi], sb + off);
                ldx4(al[mi], sb + 8192 + off);
            }
#pragma unroll
            for (int ni = 0; ni < 4; ni++) {
                uint32_t off = swz((uint32_t)((wn * 32 + ni * 8 + brow) * 64 + ks * 32 + bkh * 16));
                ldx2(bh[ni], sb + 16384 + off);
                ldx2(bl[ni], sb + 24576 + off);
            }
#pragma unroll
            for (int mi = 0; mi < 4; mi++)
#pragma unroll
                for (int ni = 0; ni < 4; ni++) {
                    mma_bf16(acc[mi][ni], ah[mi], bh[ni]);
                    mma_bf16(acc[mi][ni], ah[mi], bl[ni]);
                    mma_bf16(acc[mi][ni], al[mi], bh[ni]);
                }
        }
        __syncthreads();
    }

    // Epilogue: c0,c1 -> (r0, col..col+1); c2,c3 -> (r0+8, ...)
#pragma unroll
    for (int mi = 0; mi < 4; mi++) {
        int r0 = bm + wm * 64 + mi * 16 + (lane >> 2);
#pragma unroll
        for (int ni = 0; ni < 4; ni++) {
            int col = bn + wn * 32 + ni * 8 + (lane & 3) * 2;
            float b0 = bias[col], b1 = bias[col + 1];
            float2 v0 = make_float2(acc[mi][ni][0] + b0, acc[mi][ni][1] + b1);
            float2 v1 = make_float2(acc[mi][ni][2] + b0, acc[mi][ni][3] + b1);
            *(float2*)(C + (size_t)r0 * Nd + col) = v0;
            *(float2*)(C + (size_t)(r0 + 8) * Nd + col) = v1;
        }
    }
#undef LOAD_STAGE
}

// ---------------------------------------------------------------------------
// fp32 -> (bf16 hi, bf16 lo) split
// ---------------------------------------------------------------------------
__global__ __launch_bounds__(256) void split_bf16(
    const float4* __restrict__ src, __nv_bfloat162* __restrict__ hi,
    __nv_bfloat162* __restrict__ lo, int n4)
{
    int i = blockIdx.x * 256 + threadIdx.x;
    if (i >= n4) return;
    float4 v = src[i];
    __nv_bfloat16 h0 = __float2bfloat16(v.x), h1 = __float2bfloat16(v.y);
    __nv_bfloat16 h2 = __float2bfloat16(v.z), h3 = __float2bfloat16(v.w);
    float l0 = v.x - __bfloat162float(h0), l1 = v.y - __bfloat162float(h1);
    float l2 = v.z - __bfloat162float(h2), l3 = v.w - __bfloat162float(h3);
    hi[2 * i]     = __nv_bfloat162(h0, h1);
    hi[2 * i + 1] = __nv_bfloat162(h2, h3);
    lo[2 * i]     = __nv_bfloat162(__float2bfloat16(l0), __float2bfloat16(l1));
    lo[2 * i + 1] = __nv_bfloat162(__float2bfloat16(l2), __float2bfloat16(l3));
}

// ---------------------------------------------------------------------------
// Fused RMSNorm + interleaved RoPE (unchanged)
// ---------------------------------------------------------------------------
__global__ __launch_bounds__(256) void rmsnorm_rope(
    float* __restrict__ h, const float* __restrict__ w,
    const float* __restrict__ cosb, const float* __restrict__ sinb)
{
    const int row = blockIdx.x;
    const int t = row & (T_ - 1);
    float* hr = h + (size_t)row * D_;

    float ss = 0.f;
    for (int i = threadIdx.x; i < D_; i += 256) { float v = hr[i]; ss += v * v; }
#pragma unroll
    for (int o = 16; o > 0; o >>= 1) ss += __shfl_xor_sync(0xffffffffu, ss, o);
    __shared__ float red[8];
    __shared__ float s_inv;
    if ((threadIdx.x & 31) == 0) red[threadIdx.x >> 5] = ss;
    __syncthreads();
    if (threadIdx.x == 0) {
        float s = 0.f;
        for (int i = 0; i < 8; i++) s += red[i];
        s_inv = rsqrtf(s * (1.0f / D_) + 1e-6f);
    }
    __syncthreads();
    const float inv = s_inv;
    const float* ct = cosb + (size_t)t * D_;
    const float* st = sinb + (size_t)t * D_;
    for (int i = threadIdx.x; i < D_ / 2; i += 256) {
        int i2 = i * 2;
        float e = hr[i2] * inv * w[i2];
        float o = hr[i2 + 1] * inv * w[i2 + 1];
        hr[i2]     = e * ct[i2]     - o * st[i2];
        hr[i2 + 1] = o * ct[i2 + 1] + e * st[i2 + 1];
    }
}

// ---------------------------------------------------------------------------
// fp32 flash attention (unchanged from R1)
// ---------------------------------------------------------------------------
__global__ __launch_bounds__(256) void flash_attn(
    const float* __restrict__ Q, const float* __restrict__ K,
    const float* __restrict__ V, float* __restrict__ O)
{
    constexpr int BM = 64, BN = 64;
    constexpr int SKP = 129;
    constexpr int SVP = 132;
    constexpr int SSP = 65;
    extern __shared__ float sm[];
    float* sQ = sm;
    float* sK = sQ + BM * DH_;
    float* sV = sK + BN * SKP;
    float* sS = sV + BN * SVP;
    __shared__ float m_s[BM], l_s[BM], al_s[BM];

    const int tid = threadIdx.x;
    const int b = blockIdx.z, h = blockIdx.y;
    const int q0 = blockIdx.x * BM;
    const int tx = tid & 15, ty = tid >> 4;

    const float* Qb = Q + ((size_t)b * T_ + q0) * D_ + h * DH_;
    for (int i = tid; i < BM * (DH_ / 4); i += 256) {
        int r = i >> 5, c = (i & 31) << 2;
        *(float4*)(sQ + r * DH_ + c) = *(const float4*)(Qb + (size_t)r * D_ + c);
    }
    if (tid < BM) { m_s[tid] = -1e30f; l_s[tid] = 0.f; }

    float acc[4][8];
#pragma unroll
    for (int i = 0; i < 4; i++)
#pragma unroll
        for (int j = 0; j < 8; j++) acc[i][j] = 0.f;
    __syncthreads();

    const float scale = 0.08838834764831845f;

    for (int kt = 0; kt < T_ / BN; kt++) {
        const float* Kb = K + ((size_t)b * T_ + kt * BN) * D_ + h * DH_;
        const float* Vb = V + ((size_t)b * T_ + kt * BN) * D_ + h * DH_;
        for (int i = tid; i < BN * (DH_ / 4); i += 256) {
            int r = i >> 5, c = (i & 31) << 2;
            float4 kv = *(const float4*)(Kb + (size_t)r * D_ + c);
            sK[r * SKP + c]     = kv.x;
            sK[r * SKP + c + 1] = kv.y;
            sK[r * SKP + c + 2] = kv.z;
            sK[r * SKP + c + 3] = kv.w;
            *(float4*)(sV + r * SVP + c) = *(const float4*)(Vb + (size_t)r * D_ + c);
        }
        __syncthreads();

        float s4[4][4];
#pragma unroll
        for (int i = 0; i < 4; i++)
#pragma unroll
            for (int j = 0; j < 4; j++) s4[i][j] = 0.f;
#pragma unroll 4
        for (int d = 0; d < DH_; d++) {
            float a[4], bb[4];
#pragma unroll
            for (int i = 0; i < 4; i++) a[i] = sQ[(ty * 4 + i) * DH_ + d];
#pragma unroll
            for (int j = 0; j < 4; j++) bb[j] = sK[(tx * 4 + j) * SKP + d];
#pragma unroll
            for (int i = 0; i < 4; i++)
#pragma unroll
                for (int j = 0; j < 4; j++)
                    s4[i][j] += a[i] * bb[j];
        }
#pragma unroll
        for (int i = 0; i < 4; i++)
#pragma unroll
            for (int j = 0; j < 4; j++)
                sS[(ty * 4 + i) * SSP + tx * 4 + j] = s4[i][j] * scale;
        __syncthreads();

        if (tid < BM) {
            float* row = sS + tid * SSP;
            float mold = m_s[tid];
            float mx = mold;
            for (int j = 0; j < BN; j++) mx = fmaxf(mx, row[j]);
            float sum = 0.f;
            for (int j = 0; j < BN; j++) { float p = __expf(row[j] - mx); row[j] = p; sum += p; }
            float alpha = __expf(mold - mx);
            m_s[tid] = mx;
            l_s[tid] = l_s[tid] * alpha + sum;
            al_s[tid] = alpha;
        }
        __syncthreads();

        float al[4];
#pragma unroll
        for (int i = 0; i < 4; i++) al[i] = al_s[ty * 4 + i];
#pragma unroll
        for (int i = 0; i < 4; i++)
#pragma unroll
            for (int j = 0; j < 8; j++) acc[i][j] *= al[i];
#pragma unroll 4
        for (int k = 0; k < BN; k++) {
            float p[4];
#pragma unroll
            for (int i = 0; i < 4; i++) p[i] = sS[(ty * 4 + i) * SSP + k];
            float v8[8];
            *(float4*)&v8[0] = *(const float4*)(sV + k * SVP + tx * 8);
            *(float4*)&v8[4] = *(const float4*)(sV + k * SVP + tx * 8 + 4);
#pragma unroll
            for (int i = 0; i < 4; i++)
#pragma unroll
                for (int j = 0; j < 8; j++)
                    acc[i][j] += p[i] * v8[j];
        }
        __syncthreads();
    }

    float* Ob = O + ((size_t)b * T_ + q0) * D_ + h * DH_;
#pragma unroll
    for (int i = 0; i < 4; i++) {
        float inv = 1.f / l_s[ty * 4 + i];
        float4 o0 = make_float4(acc[i][0] * inv, acc[i][1] * inv,
                                acc[i][2] * inv, acc[i][3] * inv);
        float4 o1 = make_float4(acc[i][4] * inv, acc[i][5] * inv,
                                acc[i][6] * inv, acc[i][7] * inv);
        float* dst = Ob + (size_t)(ty * 4 + i) * D_ + tx * 8;
        *(float4*)dst = o0;
        *(float4*)(dst + 4) = o1;
    }
}

// ---------------------------------------------------------------------------
// Launch
// ---------------------------------------------------------------------------
extern "C" void kernel_launch(void* const* d_in, const int* in_sizes, int n_in,
                              void* d_out, int out_size)
{
    const float* x    = (const float*)d_in[0];
    const float* cosb = (const float*)d_in[1];
    const float* sinb = (const float*)d_in[2];
    const float* Wq   = (const float*)d_in[3];
    const float* bq   = (const float*)d_in[4];
    const float* Wk   = (const float*)d_in[5];
    const float* bk   = (const float*)d_in[6];
    const float* Wv   = (const float*)d_in[7];
    const float* bv   = (const float*)d_in[8];
    const float* qnw  = (const float*)d_in[9];
    const float* knw  = (const float*)d_in[10];
    const float* Wo   = (const float*)d_in[11];
    const float* bo   = (const float*)d_in[12];
    float* out = (float*)d_out;

    float *qp, *kp, *vp, *op;
    cudaGetSymbolAddress((void**)&qp, g_q);
    cudaGetSymbolAddress((void**)&kp, g_k);
    cudaGetSymbolAddress((void**)&vp, g_v);
    cudaGetSymbolAddress((void**)&op, g_o);
    __nv_bfloat16 *xh, *xl, *oh, *ol, *wqh, *wql, *wkh, *wkl, *wvh, *wvl, *woh, *wol;
    cudaGetSymbolAddress((void**)&xh, g_xh);   cudaGetSymbolAddress((void**)&xl, g_xl);
    cudaGetSymbolAddress((void**)&oh, g_oh);   cudaGetSymbolAddress((void**)&ol, g_ol);
    cudaGetSymbolAddress((void**)&wqh, g_wqh); cudaGetSymbolAddress((void**)&wql, g_wql);
    cudaGetSymbolAddress((void**)&wkh, g_wkh); cudaGetSymbolAddress((void**)&wkl, g_wkl);
    cudaGetSymbolAddress((void**)&wvh, g_wvh); cudaGetSymbolAddress((void**)&wvl, g_wvl);
    cudaGetSymbolAddress((void**)&woh, g_woh); cudaGetSymbolAddress((void**)&wol, g_wol);

    const int nx4 = M_ * D_ / 4;
    const int nw4 = D_ * D_ / 4;
    split_bf16<<<nx4 / 256, 256>>>((const float4*)x,  (__nv_bfloat162*)xh,  (__nv_bfloat162*)xl,  nx4);
    split_bf16<<<nw4 / 256, 256>>>((const float4*)Wq, (__nv_bfloat162*)wqh, (__nv_bfloat162*)wql, nw4);
    split_bf16<<<nw4 / 256, 256>>>((const float4*)Wk, (__nv_bfloat162*)wkh, (__nv_bfloat162*)wkl, nw4);
    split_bf16<<<nw4 / 256, 256>>>((const float4*)Wv, (__nv_bfloat162*)wvh, (__nv_bfloat162*)wvl, nw4);
    split_bf16<<<nw4 / 256, 256>>>((const float4*)Wo, (__nv_bfloat162*)woh, (__nv_bfloat162*)wol, nw4);

    cudaFuncSetAttribute(gemm_mma_split, cudaFuncAttributeMaxDynamicSharedMemorySize, GEMM_SMEM);
    dim3 ggrid(D_ / 128, M_ / 128);   // (16, 32)
    gemm_mma_split<<<ggrid, 256, GEMM_SMEM>>>(xh, xl, wqh, wql, bq, qp, M_, D_, D_);
    gemm_mma_split<<<ggrid, 256, GEMM_SMEM>>>(xh, xl, wkh, wkl, bk, kp, M_, D_, D_);
    gemm_mma_split<<<ggrid, 256, GEMM_SMEM>>>(xh, xl, wvh, wvl, bv, vp, M_, D_, D_);

    rmsnorm_rope<<<M_, 256>>>(qp, qnw, cosb, sinb);
    rmsnorm_rope<<<M_, 256>>>(kp, knw, cosb, sinb);

    const int flash_smem = (64 * 128 + 64 * 129 + 64 * 132 + 64 * 65) * 4;
    cudaFuncSetAttribute(flash_attn, cudaFuncAttributeMaxDynamicSharedMemorySize, flash_smem);
    flash_attn<<<dim3(T_ / 64, H_, B_), 256, flash_smem>>>(qp, kp, vp, op);

    split_bf16<<<nx4 / 256, 256>>>((const float4*)op, (__nv_bfloat162*)oh, (__nv_bfloat162*)ol, nx4);
    gemm_mma_split<<<ggrid, 256, GEMM_SMEM>>>(oh, ol, woh, wol, bo, out, M_, D_, D_);
}

// round 6
// speedup vs baseline: 3.1477x; 2.0777x over previous
#include <cuda_runtime.h>
#include <cuda_bf16.h>
#include <math.h>
#include <stdint.h>

// Problem constants
#define B_  2
#define T_  2048
#define D_  2048
#define H_  16
#define DH_ 128
#define M_  4096            // B_*T_

// ---------------- scratch (__device__ globals; no allocs allowed) ----------
__device__ __align__(256) float g_q[8388608];
__device__ __align__(256) float g_k[8388608];
__device__ __align__(256) float g_v[8388608];
__device__ __align__(256) float g_o[8388608];
__device__ __align__(256) __nv_bfloat16 g_xh[8388608], g_xl[8388608];
__device__ __align__(256) __nv_bfloat16 g_oh[8388608], g_ol[8388608];
__device__ __align__(256) __nv_bfloat16 g_qh[8388608], g_ql[8388608];
__device__ __align__(256) __nv_bfloat16 g_kh[8388608], g_kl[8388608];
__device__ __align__(256) __nv_bfloat16 g_vh[8388608], g_vl[8388608];
__device__ __align__(256) __nv_bfloat16 g_wqh[4194304], g_wql[4194304];
__device__ __align__(256) __nv_bfloat16 g_wkh[4194304], g_wkl[4194304];
__device__ __align__(256) __nv_bfloat16 g_wvh[4194304], g_wvl[4194304];
__device__ __align__(256) __nv_bfloat16 g_woh[4194304], g_wol[4194304];

// ---------------- PTX helpers ----------------------------------------------
__device__ __forceinline__ uint32_t smem_u32(const void* p) {
    uint32_t a;
    asm("{ .reg .u64 t; cvta.to.shared.u64 t, %1; cvt.u32.u64 %0, t; }" : "=r"(a) : "l"(p));
    return a;
}
__device__ __forceinline__ void cpa16(uint32_t s, const void* g) {
    asm volatile("cp.async.cg.shared.global [%0], [%1], 16;" :: "r"(s), "l"(g));
}
__device__ __forceinline__ void ldx4(uint32_t* d, uint32_t addr) {
    asm volatile("ldmatrix.sync.aligned.m8n8.x4.shared.b16 {%0,%1,%2,%3}, [%4];"
                 : "=r"(d[0]), "=r"(d[1]), "=r"(d[2]), "=r"(d[3]) : "r"(addr));
}
__device__ __forceinline__ void ldx2(uint32_t* d, uint32_t addr) {
    asm volatile("ldmatrix.sync.aligned.m8n8.x2.shared.b16 {%0,%1}, [%2];"
                 : "=r"(d[0]), "=r"(d[1]) : "r"(addr));
}
__device__ __forceinline__ void ldx2t(uint32_t* d, uint32_t addr) {
    asm volatile("ldmatrix.sync.aligned.m8n8.x2.trans.shared.b16 {%0,%1}, [%2];"
                 : "=r"(d[0]), "=r"(d[1]) : "r"(addr));
}
__device__ __forceinline__ void mma_bf16(float* c, const uint32_t* a, const uint32_t* b) {
    asm volatile(
        "mma.sync.aligned.m16n8k16.row.col.f32.bf16.bf16.f32 "
        "{%0,%1,%2,%3}, {%4,%5,%6,%7}, {%8,%9}, {%0,%1,%2,%3};"
        : "+f"(c[0]), "+f"(c[1]), "+f"(c[2]), "+f"(c[3])
        : "r"(a[0]), "r"(a[1]), "r"(a[2]), "r"(a[3]), "r"(b[0]), "r"(b[1]));
}
__device__ __forceinline__ uint32_t pk(__nv_bfloat16 a, __nv_bfloat16 b) {
    __nv_bfloat162 t(a, b);
    return *(uint32_t*)&t;
}
// swizzle for 64-byte rows (GEMM tiles)
__device__ __forceinline__ uint32_t swz(uint32_t off) { return off ^ ((off >> 3) & 0x30); }

// ---------------------------------------------------------------------------
// mma.sync GEMM-NT with bf16 2-term split + fp32 accumulation. (unchanged, passing)
// ---------------------------------------------------------------------------
#define STAGE_B 32768
#define GEMM_SMEM (3 * STAGE_B)

__global__ __launch_bounds__(256, 1) void gemm_mma_split(
    const __nv_bfloat16* __restrict__ Ah, const __nv_bfloat16* __restrict__ Al,
    const __nv_bfloat16* __restrict__ Bh, const __nv_bfloat16* __restrict__ Bl,
    const float* __restrict__ bias, float* __restrict__ C,
    int Md, int Nd, int Kd)
{
    extern __shared__ __align__(1024) unsigned char smem[];
    const int tid = threadIdx.x;
    const int wid = tid >> 5;
    const int lane = tid & 31;
    const int wm = wid >> 2;
    const int wn = wid & 3;
    const int bm = blockIdx.y * 128;
    const int bn = blockIdx.x * 128;
    const uint32_t sbase = smem_u32(smem);
    const int nchunk = Kd >> 5;

#define LOAD_STAGE(stage, k0)                                                   \
    {                                                                            \
        uint32_t sb = sbase + (stage) * STAGE_B;                                 \
        _Pragma("unroll")                                                        \
        for (int j = 0; j < 2; j++) {                                            \
            int idx = tid + j * 256;                                             \
            int r = idx >> 2, c = idx & 3;                                       \
            uint32_t so = swz((uint32_t)(r * 64 + c * 16));                      \
            size_t ga = (size_t)(bm + r) * Kd + (k0) + c * 8;                    \
            size_t gb = (size_t)(bn + r) * Kd + (k0) + c * 8;                    \
            cpa16(sb + so,         Ah + ga);                                     \
            cpa16(sb + 8192 + so,  Al + ga);                                     \
            cpa16(sb + 16384 + so, Bh + gb);                                     \
            cpa16(sb + 24576 + so, Bl + gb);                                     \
        }                                                                        \
        asm volatile("cp.async.commit_group;" ::: "memory");                     \
    }

    LOAD_STAGE(0, 0)
    LOAD_STAGE(1, 32)

    float acc[4][4][4];
#pragma unroll
    for (int i = 0; i < 4; i++)
#pragma unroll
        for (int j = 0; j < 4; j++)
#pragma unroll
            for (int l = 0; l < 4; l++) acc[i][j][l] = 0.f;

    const int arow = lane & 15;
    const int akh = lane >> 4;
    const int bln = lane & 15;
    const int brow = bln & 7;
    const int bkh = (bln >> 3) & 1;

    for (int i = 0; i < nchunk; i++) {
        if (i + 2 < nchunk) {
            LOAD_STAGE((i + 2) % 3, (i + 2) * 32)
            asm volatile("cp.async.wait_group 2;" ::: "memory");
        } else if (i + 1 < nchunk) {
            asm volatile("cp.async.wait_group 1;" ::: "memory");
        } else {
            asm volatile("cp.async.wait_group 0;" ::: "memory");
        }
        __syncthreads();

        const uint32_t sb = sbase + (i % 3) * STAGE_B;
#pragma unroll
        for (int ks = 0; ks < 2; ks++) {
            uint32_t ah[4][4], al[4][4], bh[4][2], bl[4][2];
#pragma unroll
            for (int mi = 0; mi < 4; mi++) {
                uint32_t off = swz((uint32_t)((wm * 64 + mi * 16 + arow) * 64 + ks * 32 + akh * 16));
                ldx4(ah[mi], sb + off);
                ldx4(al[mi], sb + 8192 + off);
            }
#pragma unroll
            for (int ni = 0; ni < 4; ni++) {
                uint32_t off = swz((uint32_t)((wn * 32 + ni * 8 + brow) * 64 + ks * 32 + bkh * 16));
                ldx2(bh[ni], sb + 16384 + off);
                ldx2(bl[ni], sb + 24576 + off);
            }
#pragma unroll
            for (int mi = 0; mi < 4; mi++)
#pragma unroll
                for (int ni = 0; ni < 4; ni++) {
                    mma_bf16(acc[mi][ni], ah[mi], bh[ni]);
                    mma_bf16(acc[mi][ni], ah[mi], bl[ni]);
                    mma_bf16(acc[mi][ni], al[mi], bh[ni]);
                }
        }
        __syncthreads();
    }

#pragma unroll
    for (int mi = 0; mi < 4; mi++) {
        int r0 = bm + wm * 64 + mi * 16 + (lane >> 2);
#pragma unroll
        for (int ni = 0; ni < 4; ni++) {
            int col = bn + wn * 32 + ni * 8 + (lane & 3) * 2;
            float b0 = bias[col], b1 = bias[col + 1];
            float2 v0 = make_float2(acc[mi][ni][0] + b0, acc[mi][ni][1] + b1);
            float2 v1 = make_float2(acc[mi][ni][2] + b0, acc[mi][ni][3] + b1);
            *(float2*)(C + (size_t)r0 * Nd + col) = v0;
            *(float2*)(C + (size_t)(r0 + 8) * Nd + col) = v1;
        }
    }
#undef LOAD_STAGE
}

// ---------------------------------------------------------------------------
// fp32 -> (bf16 hi, bf16 lo) split
// ---------------------------------------------------------------------------
__global__ __launch_bounds__(256) void split_bf16(
    const float4* __restrict__ src, __nv_bfloat162* __restrict__ hi,
    __nv_bfloat162* __restrict__ lo, int n4)
{
    int i = blockIdx.x * 256 + threadIdx.x;
    if (i >= n4) return;
    float4 v = src[i];
    __nv_bfloat16 h0 = __float2bfloat16(v.x), h1 = __float2bfloat16(v.y);
    __nv_bfloat16 h2 = __float2bfloat16(v.z), h3 = __float2bfloat16(v.w);
    float l0 = v.x - __bfloat162float(h0), l1 = v.y - __bfloat162float(h1);
    float l2 = v.z - __bfloat162float(h2), l3 = v.w - __bfloat162float(h3);
    hi[2 * i]     = __nv_bfloat162(h0, h1);
    hi[2 * i + 1] = __nv_bfloat162(h2, h3);
    lo[2 * i]     = __nv_bfloat162(__float2bfloat16(l0), __float2bfloat16(l1));
    lo[2 * i + 1] = __nv_bfloat162(__float2bfloat16(l2), __float2bfloat16(l3));
}

// ---------------------------------------------------------------------------
// Fused RMSNorm + interleaved RoPE, writing bf16 hi/lo splits directly.
// ---------------------------------------------------------------------------
__global__ __launch_bounds__(256) void rmsnorm_rope_split(
    const float* __restrict__ h, const float* __restrict__ w,
    const float* __restrict__ cosb, const float* __restrict__ sinb,
    __nv_bfloat16* __restrict__ outh, __nv_bfloat16* __restrict__ outl)
{
    const int row = blockIdx.x;
    const int t = row & (T_ - 1);
    const float* hr = h + (size_t)row * D_;

    float ss = 0.f;
    for (int i = threadIdx.x; i < D_; i += 256) { float v = hr[i]; ss += v * v; }
#pragma unroll
    for (int o = 16; o > 0; o >>= 1) ss += __shfl_xor_sync(0xffffffffu, ss, o);
    __shared__ float red[8];
    __shared__ float s_inv;
    if ((threadIdx.x & 31) == 0) red[threadIdx.x >> 5] = ss;
    __syncthreads();
    if (threadIdx.x == 0) {
        float s = 0.f;
        for (int i = 0; i < 8; i++) s += red[i];
        s_inv = rsqrtf(s * (1.0f / D_) + 1e-6f);
    }
    __syncthreads();
    const float inv = s_inv;
    const float* ct = cosb + (size_t)t * D_;
    const float* st = sinb + (size_t)t * D_;
    __nv_bfloat162* oh2 = (__nv_bfloat162*)(outh + (size_t)row * D_);
    __nv_bfloat162* ol2 = (__nv_bfloat162*)(outl + (size_t)row * D_);
    for (int i = threadIdx.x; i < D_ / 2; i += 256) {
        int i2 = i * 2;
        float e = hr[i2] * inv * w[i2];
        float o = hr[i2 + 1] * inv * w[i2 + 1];
        float v0 = e * ct[i2]     - o * st[i2];
        float v1 = o * ct[i2 + 1] + e * st[i2 + 1];
        __nv_bfloat16 h0 = __float2bfloat16(v0), h1 = __float2bfloat16(v1);
        oh2[i] = __nv_bfloat162(h0, h1);
        ol2[i] = __nv_bfloat162(__float2bfloat16(v0 - __bfloat162float(h0)),
                                __float2bfloat16(v1 - __bfloat162float(h1)));
    }
}

// ---------------------------------------------------------------------------
// bf16-split mma.sync flash attention (non-causal).
// BM=64 (4 warps x 16 rows), BN=64 per iter, Dh=128.
// smem: 2 stages x (Kh 16K | Kl 16K | Vh 16K | Vl 16K) = 128 KB.
// grid = (T/64, H, B), 128 threads.
// ---------------------------------------------------------------------------
#define FA_STAGE 65536

__global__ __launch_bounds__(128, 1) void flash_attn_mma(
    const __nv_bfloat16* __restrict__ Qh, const __nv_bfloat16* __restrict__ Ql,
    const __nv_bfloat16* __restrict__ Kh, const __nv_bfloat16* __restrict__ Kl,
    const __nv_bfloat16* __restrict__ Vh, const __nv_bfloat16* __restrict__ Vl,
    float* __restrict__ O)
{
    extern __shared__ __align__(1024) unsigned char smem[];
    const int tid = threadIdx.x;
    const int wid = tid >> 5, lane = tid & 31;
    const int b = blockIdx.z, h = blockIdx.y;
    const int q0 = blockIdx.x * 64;
    const uint32_t sbase = smem_u32(smem);
    const size_t rowbase = ((size_t)b * T_) * D_ + h * DH_;   // add row*D_ + col

#define LOADKV(it_, stg)                                                         \
    {                                                                            \
        uint32_t sb_ = sbase + (stg) * FA_STAGE;                                 \
        size_t base_ = rowbase + (size_t)((it_) * 64) * D_;                      \
        for (int t = tid; t < 1024; t += 128) {                                  \
            int r_ = t >> 4, c_ = t & 15;                                        \
            uint32_t ph_ = r_ * 256 + ((c_ ^ (r_ & 7)) << 4);                    \
            size_t g_ = base_ + (size_t)r_ * D_ + c_ * 8;                        \
            cpa16(sb_ + ph_,          Kh + g_);                                  \
            cpa16(sb_ + 16384 + ph_,  Kl + g_);                                  \
            cpa16(sb_ + 32768 + ph_,  Vh + g_);                                  \
            cpa16(sb_ + 49152 + ph_,  Vl + g_);                                  \
        }                                                                        \
        asm volatile("cp.async.commit_group;" ::: "memory");                     \
    }

    // ---- stage Q (hi at 0, lo at +16K), build register fragments ----
    for (int t = tid; t < 1024; t += 128) {
        int r = t >> 4, c = t & 15;
        uint32_t ph = r * 256 + ((c ^ (r & 7)) << 4);
        size_t g = rowbase + (size_t)(q0 + r) * D_ + c * 8;
        cpa16(sbase + ph, Qh + g);
        cpa16(sbase + 16384 + ph, Ql + g);
    }
    asm volatile("cp.async.commit_group;" ::: "memory");
    asm volatile("cp.async.wait_group 0;" ::: "memory");
    __syncthreads();

    uint32_t qh[8][4], ql[8][4];
    {
        int r = wid * 16 + (lane & 15);
        int khalf = lane >> 4;
#pragma unroll
        for (int kk = 0; kk < 8; kk++) {
            int chunk = kk * 2 + khalf;
            uint32_t ph = r * 256 + ((chunk ^ (r & 7)) << 4);
            ldx4(qh[kk], sbase + ph);
            ldx4(ql[kk], sbase + 16384 + ph);
        }
    }
    __syncthreads();

    float o[16][4];
#pragma unroll
    for (int i = 0; i < 16; i++)
#pragma unroll
        for (int j = 0; j < 4; j++) o[i][j] = 0.f;
    float m0 = -1e30f, m1 = -1e30f, l0 = 0.f, l1 = 0.f;

    LOADKV(0, 0)
    LOADKV(1, 1)

    const float scale = 0.08838834764831845f;
    const int NIT = T_ / 64;   // 32

    for (int it = 0; it < NIT; it++) {
        if (it < NIT - 1) { asm volatile("cp.async.wait_group 1;" ::: "memory"); }
        else              { asm volatile("cp.async.wait_group 0;" ::: "memory"); }
        __syncthreads();
        const uint32_t sb = sbase + (it & 1) * FA_STAGE;

        // ---- S = Q K^T (3-pass split) ----
        float s[8][4];
#pragma unroll
        for (int n = 0; n < 8; n++)
#pragma unroll
            for (int j = 0; j < 4; j++) s[n][j] = 0.f;

        const int krow_lo = lane & 7;
        const int kkh = ((lane & 15) >> 3) & 1;
#pragma unroll
        for (int kk = 0; kk < 8; kk++) {
#pragma unroll
            for (int n = 0; n < 8; n++) {
                int r = n * 8 + krow_lo;
                int chunk = kk * 2 + kkh;
                uint32_t ph = r * 256 + ((chunk ^ (r & 7)) << 4);
                uint32_t bh[2], bl[2];
                ldx2(bh, sb + ph);
                ldx2(bl, sb + 16384 + ph);
                mma_bf16(s[n], qh[kk], bh);
                mma_bf16(s[n], qh[kk], bl);
                mma_bf16(s[n], ql[kk], bh);
            }
        }

        // ---- online softmax (rows r_low = lane>>2, r_high = +8) ----
#pragma unroll
        for (int n = 0; n < 8; n++)
#pragma unroll
            for (int j = 0; j < 4; j++) s[n][j] *= scale;

        float cm0 = -1e30f, cm1 = -1e30f;
#pragma unroll
        for (int n = 0; n < 8; n++) {
            cm0 = fmaxf(cm0, fmaxf(s[n][0], s[n][1]));
            cm1 = fmaxf(cm1, fmaxf(s[n][2], s[n][3]));
        }
        cm0 = fmaxf(cm0, __shfl_xor_sync(0xffffffffu, cm0, 1));
        cm0 = fmaxf(cm0, __shfl_xor_sync(0xffffffffu, cm0, 2));
        cm1 = fmaxf(cm1, __shfl_xor_sync(0xffffffffu, cm1, 1));
        cm1 = fmaxf(cm1, __shfl_xor_sync(0xffffffffu, cm1, 2));
        float mn0 = fmaxf(m0, cm0), mn1 = fmaxf(m1, cm1);
        float a0 = __expf(m0 - mn0), a1 = __expf(m1 - mn1);
        float sum0 = 0.f, sum1 = 0.f;
#pragma unroll
        for (int n = 0; n < 8; n++) {
            s[n][0] = __expf(s[n][0] - mn0);
            s[n][1] = __expf(s[n][1] - mn0);
            s[n][2] = __expf(s[n][2] - mn1);
            s[n][3] = __expf(s[n][3] - mn1);
            sum0 += s[n][0] + s[n][1];
            sum1 += s[n][2] + s[n][3];
        }
        sum0 += __shfl_xor_sync(0xffffffffu, sum0, 1);
        sum0 += __shfl_xor_sync(0xffffffffu, sum0, 2);
        sum1 += __shfl_xor_sync(0xffffffffu, sum1, 1);
        sum1 += __shfl_xor_sync(0xffffffffu, sum1, 2);
        l0 = l0 * a0 + sum0;
        l1 = l1 * a1 + sum1;
        m0 = mn0; m1 = mn1;
#pragma unroll
        for (int ni = 0; ni < 16; ni++) {
            o[ni][0] *= a0; o[ni][1] *= a0;
            o[ni][2] *= a1; o[ni][3] *= a1;
        }

        // ---- O += P V (3-pass split), P split per k-step ----
        const int vrow = lane & 15;
#pragma unroll
        for (int j = 0; j < 4; j++) {
            uint32_t ph4[4], pl4[4];
#pragma unroll
            for (int half = 0; half < 2; half++) {
                float x0 = s[2 * j + half][0], x1 = s[2 * j + half][1];
                float x2 = s[2 * j + half][2], x3 = s[2 * j + half][3];
                __nv_bfloat16 h0 = __float2bfloat16(x0), h1 = __float2bfloat16(x1);
                __nv_bfloat16 h2 = __float2bfloat16(x2), h3 = __float2bfloat16(x3);
                ph4[2 * half]     = pk(h0, h1);
                ph4[2 * half + 1] = pk(h2, h3);
                pl4[2 * half]     = pk(__float2bfloat16(x0 - __bfloat162float(h0)),
                                       __float2bfloat16(x1 - __bfloat162float(h1)));
                pl4[2 * half + 1] = pk(__float2bfloat16(x2 - __bfloat162float(h2)),
                                       __float2bfloat16(x3 - __bfloat162float(h3)));
            }
            // reorder: a-frag = {rl_klow, rh_klow, rl_khigh, rh_khigh}
            uint32_t pa[4] = { ph4[0], ph4[1], ph4[2], ph4[3] };
            uint32_t pb[4] = { pl4[0], pl4[1], pl4[2], pl4[3] };
            int r = j * 16 + vrow;
#pragma unroll
            for (int ni = 0; ni < 16; ni++) {
                uint32_t ph = r * 256 + ((ni ^ (r & 7)) << 4);
                uint32_t vh[2], vl[2];
                ldx2t(vh, sb + 32768 + ph);
                ldx2t(vl, sb + 49152 + ph);
                mma_bf16(o[ni], pa, vh);
                mma_bf16(o[ni], pa, vl);
                mma_bf16(o[ni], pb, vh);
            }
        }
        __syncthreads();
        if (it + 2 < NIT) { LOADKV(it + 2, it & 1) }
    }

    // ---- store ----
    float i0 = 1.f / l0, i1 = 1.f / l1;
    int r_lo = q0 + wid * 16 + (lane >> 2);
#pragma unroll
    for (int ni = 0; ni < 16; ni++) {
        int col = ni * 8 + (lane & 3) * 2;
        float2 v0 = make_float2(o[ni][0] * i0, o[ni][1] * i0);
        float2 v1 = make_float2(o[ni][2] * i1, o[ni][3] * i1);
        *(float2*)(O + rowbase + (size_t)r_lo * D_ + col) = v0;
        *(float2*)(O + rowbase + (size_t)(r_lo + 8) * D_ + col) = v1;
    }
#undef LOADKV
}

// ---------------------------------------------------------------------------
// Launch
// ---------------------------------------------------------------------------
extern "C" void kernel_launch(void* const* d_in, const int* in_sizes, int n_in,
                              void* d_out, int out_size)
{
    const float* x    = (const float*)d_in[0];
    const float* cosb = (const float*)d_in[1];
    const float* sinb = (const float*)d_in[2];
    const float* Wq   = (const float*)d_in[3];
    const float* bq   = (const float*)d_in[4];
    const float* Wk   = (const float*)d_in[5];
    const float* bk   = (const float*)d_in[6];
    const float* Wv   = (const float*)d_in[7];
    const float* bv   = (const float*)d_in[8];
    const float* qnw  = (const float*)d_in[9];
    const float* knw  = (const float*)d_in[10];
    const float* Wo   = (const float*)d_in[11];
    const float* bo   = (const float*)d_in[12];
    float* out = (float*)d_out;

    float *qp, *kp, *vp, *op;
    cudaGetSymbolAddress((void**)&qp, g_q);
    cudaGetSymbolAddress((void**)&kp, g_k);
    cudaGetSymbolAddress((void**)&vp, g_v);
    cudaGetSymbolAddress((void**)&op, g_o);
    __nv_bfloat16 *xh, *xl, *oh, *ol, *qhp, *qlp, *khp, *klp, *vhp, *vlp;
    __nv_bfloat16 *wqh, *wql, *wkh, *wkl, *wvh, *wvl, *woh, *wol;
    cudaGetSymbolAddress((void**)&xh, g_xh);   cudaGetSymbolAddress((void**)&xl, g_xl);
    cudaGetSymbolAddress((void**)&oh, g_oh);   cudaGetSymbolAddress((void**)&ol, g_ol);
    cudaGetSymbolAddress((void**)&qhp, g_qh);  cudaGetSymbolAddress((void**)&qlp, g_ql);
    cudaGetSymbolAddress((void**)&khp, g_kh);  cudaGetSymbolAddress((void**)&klp, g_kl);
    cudaGetSymbolAddress((void**)&vhp, g_vh);  cudaGetSymbolAddress((void**)&vlp, g_vl);
    cudaGetSymbolAddress((void**)&wqh, g_wqh); cudaGetSymbolAddress((void**)&wql, g_wql);
    cudaGetSymbolAddress((void**)&wkh, g_wkh); cudaGetSymbolAddress((void**)&wkl, g_wkl);
    cudaGetSymbolAddress((void**)&wvh, g_wvh); cudaGetSymbolAddress((void**)&wvl, g_wvl);
    cudaGetSymbolAddress((void**)&woh, g_woh); cudaGetSymbolAddress((void**)&wol, g_wol);

    const int nx4 = M_ * D_ / 4;
    const int nw4 = D_ * D_ / 4;
    split_bf16<<<nx4 / 256, 256>>>((const float4*)x,  (__nv_bfloat162*)xh,  (__nv_bfloat162*)xl,  nx4);
    split_bf16<<<nw4 / 256, 256>>>((const float4*)Wq, (__nv_bfloat162*)wqh, (__nv_bfloat162*)wql, nw4);
    split_bf16<<<nw4 / 256, 256>>>((const float4*)Wk, (__nv_bfloat162*)wkh, (__nv_bfloat162*)wkl, nw4);
    split_bf16<<<nw4 / 256, 256>>>((const float4*)Wv, (__nv_bfloat162*)wvh, (__nv_bfloat162*)wvl, nw4);
    split_bf16<<<nw4 / 256, 256>>>((const float4*)Wo, (__nv_bfloat162*)woh, (__nv_bfloat162*)wol, nw4);

    cudaFuncSetAttribute(gemm_mma_split, cudaFuncAttributeMaxDynamicSharedMemorySize, GEMM_SMEM);
    dim3 ggrid(D_ / 128, M_ / 128);
    gemm_mma_split<<<ggrid, 256, GEMM_SMEM>>>(xh, xl, wqh, wql, bq, qp, M_, D_, D_);
    gemm_mma_split<<<ggrid, 256, GEMM_SMEM>>>(xh, xl, wkh, wkl, bk, kp, M_, D_, D_);
    gemm_mma_split<<<ggrid, 256, GEMM_SMEM>>>(xh, xl, wvh, wvl, bv, vp, M_, D_, D_);

    rmsnorm_rope_split<<<M_, 256>>>(qp, qnw, cosb, sinb, qhp, qlp);
    rmsnorm_rope_split<<<M_, 256>>>(kp, knw, cosb, sinb, khp, klp);
    split_bf16<<<nx4 / 256, 256>>>((const float4*)vp, (__nv_bfloat162*)vhp, (__nv_bfloat162*)vlp, nx4);

    cudaFuncSetAttribute(flash_attn_mma, cudaFuncAttributeMaxDynamicSharedMemorySize, 2 * FA_STAGE);
    flash_attn_mma<<<dim3(T_ / 64, H_, B_), 128, 2 * FA_STAGE>>>(qhp, qlp, khp, klp, vhp, vlp, op);

    split_bf16<<<nx4 / 256, 256>>>((const float4*)op, (__nv_bfloat162*)oh, (__nv_bfloat162*)ol, nx4);
    gemm_mma_split<<<ggrid, 256, GEMM_SMEM>>>(oh, ol, woh, wol, bo, out, M_, D_, D_);
}

// round 7
// speedup vs baseline: 3.3955x; 1.0787x over previous
#include <cuda_runtime.h>
#include <cuda_bf16.h>
#include <math.h>
#include <stdint.h>

// Problem constants
#define B_  2
#define T_  2048
#define D_  2048
#define H_  16
#define DH_ 128
#define M_  4096            // B_*T_

// ---------------- scratch (__device__ globals; no allocs allowed) ----------
__device__ __align__(256) float g_q[8388608];
__device__ __align__(256) float g_k[8388608];
__device__ __align__(256) __nv_bfloat16 g_xh[8388608], g_xl[8388608];
__device__ __align__(256) __nv_bfloat16 g_oh[8388608], g_ol[8388608];
__device__ __align__(256) __nv_bfloat16 g_qh[8388608], g_ql[8388608];
__device__ __align__(256) __nv_bfloat16 g_kh[8388608], g_kl[8388608];
__device__ __align__(256) __nv_bfloat16 g_vh[8388608], g_vl[8388608];
__device__ __align__(256) __nv_bfloat16 g_wqh[4194304], g_wql[4194304];
__device__ __align__(256) __nv_bfloat16 g_wkh[4194304], g_wkl[4194304];
__device__ __align__(256) __nv_bfloat16 g_wvh[4194304], g_wvl[4194304];
__device__ __align__(256) __nv_bfloat16 g_woh[4194304], g_wol[4194304];

// ---------------- PTX helpers ----------------------------------------------
__device__ __forceinline__ uint32_t smem_u32(const void* p) {
    uint32_t a;
    asm("{ .reg .u64 t; cvta.to.shared.u64 t, %1; cvt.u32.u64 %0, t; }" : "=r"(a) : "l"(p));
    return a;
}
__device__ __forceinline__ void cpa16(uint32_t s, const void* g) {
    asm volatile("cp.async.cg.shared.global [%0], [%1], 16;" :: "r"(s), "l"(g));
}
__device__ __forceinline__ void ldx4(uint32_t* d, uint32_t addr) {
    asm volatile("ldmatrix.sync.aligned.m8n8.x4.shared.b16 {%0,%1,%2,%3}, [%4];"
                 : "=r"(d[0]), "=r"(d[1]), "=r"(d[2]), "=r"(d[3]) : "r"(addr));
}
__device__ __forceinline__ void ldx2(uint32_t* d, uint32_t addr) {
    asm volatile("ldmatrix.sync.aligned.m8n8.x2.shared.b16 {%0,%1}, [%2];"
                 : "=r"(d[0]), "=r"(d[1]) : "r"(addr));
}
__device__ __forceinline__ void ldx2t(uint32_t* d, uint32_t addr) {
    asm volatile("ldmatrix.sync.aligned.m8n8.x2.trans.shared.b16 {%0,%1}, [%2];"
                 : "=r"(d[0]), "=r"(d[1]) : "r"(addr));
}
__device__ __forceinline__ void mma_bf16(float* c, const uint32_t* a, const uint32_t* b) {
    asm volatile(
        "mma.sync.aligned.m16n8k16.row.col.f32.bf16.bf16.f32 "
        "{%0,%1,%2,%3}, {%4,%5,%6,%7}, {%8,%9}, {%0,%1,%2,%3};"
        : "+f"(c[0]), "+f"(c[1]), "+f"(c[2]), "+f"(c[3])
        : "r"(a[0]), "r"(a[1]), "r"(a[2]), "r"(a[3]), "r"(b[0]), "r"(b[1]));
}
__device__ __forceinline__ uint32_t pk(__nv_bfloat16 a, __nv_bfloat16 b) {
    __nv_bfloat162 t(a, b);
    return *(uint32_t*)&t;
}
__device__ __forceinline__ __nv_bfloat162 split_hi2(float a, float b, __nv_bfloat162& lo) {
    __nv_bfloat16 h0 = __float2bfloat16(a), h1 = __float2bfloat16(b);
    lo = __nv_bfloat162(__float2bfloat16(a - __bfloat162float(h0)),
                        __float2bfloat16(b - __bfloat162float(h1)));
    return __nv_bfloat162(h0, h1);
}
// swizzle for 64-byte rows
__device__ __forceinline__ uint32_t swz(uint32_t off) { return off ^ ((off >> 3) & 0x30); }

// ---------------------------------------------------------------------------
// mma.sync GEMM-NT, bf16 2-term split, fp32 accum, fat warp tiles.
// C[m][n] = sum_k (Ah+Al)[m][k]*(Bh+Bl)[n][k] + bias[n]   (Al*Bl dropped)
// BM=128, BN=256, BK=32. 256 threads = 8 warps (2m x 4n), warp tile 64x64.
// 3 smem stages x 48KB (Ah 8K | Al 8K | Bh 16K | Bl 16K).
// Output: fp32 C (if non-null) and/or bf16 hi/lo split (if non-null).
// ---------------------------------------------------------------------------
#define GSTAGE 49152
#define GEMM_SMEM (3 * GSTAGE)

__global__ __launch_bounds__(256, 1) void gemm_mma_split(
    const __nv_bfloat16* __restrict__ Ah, const __nv_bfloat16* __restrict__ Al,
    const __nv_bfloat16* __restrict__ Bh, const __nv_bfloat16* __restrict__ Bl,
    const float* __restrict__ bias, float* __restrict__ C,
    __nv_bfloat16* __restrict__ OutH, __nv_bfloat16* __restrict__ OutL,
    int Md, int Nd, int Kd)
{
    extern __shared__ __align__(1024) unsigned char smem[];
    const int tid = threadIdx.x;
    const int wid = tid >> 5;
    const int lane = tid & 31;
    const int wm = wid >> 2;              // 0..1
    const int wn = wid & 3;               // 0..3
    const int bm = blockIdx.y * 128;
    const int bn = blockIdx.x * 256;
    const uint32_t sbase = smem_u32(smem);
    const int nchunk = Kd >> 5;           // 64

#define LOAD_STAGE(stage, k0)                                                   \
    {                                                                            \
        uint32_t sb = sbase + (stage) * GSTAGE;                                  \
        _Pragma("unroll")                                                        \
        for (int j = 0; j < 2; j++) {                                            \
            int idx = tid + j * 256;                                             \
            int r = idx >> 2, c = idx & 3;                                       \
            uint32_t so = swz((uint32_t)(r * 64 + c * 16));                      \
            size_t ga = (size_t)(bm + r) * Kd + (k0) + c * 8;                    \
            cpa16(sb + so,        Ah + ga);                                      \
            cpa16(sb + 8192 + so, Al + ga);                                      \
        }                                                                        \
        _Pragma("unroll")                                                        \
        for (int j = 0; j < 4; j++) {                                            \
            int idx = tid + j * 256;                                             \
            int r = idx >> 2, c = idx & 3;                                       \
            uint32_t so = swz((uint32_t)(r * 64 + c * 16));                      \
            size_t gb = (size_t)(bn + r) * Kd + (k0) + c * 8;                    \
            cpa16(sb + 16384 + so, Bh + gb);                                     \
            cpa16(sb + 32768 + so, Bl + gb);                                     \
        }                                                                        \
        asm volatile("cp.async.commit_group;" ::: "memory");                     \
    }

    LOAD_STAGE(0, 0)
    LOAD_STAGE(1, 32)

    float acc[4][8][4];
#pragma unroll
    for (int i = 0; i < 4; i++)
#pragma unroll
        for (int j = 0; j < 8; j++)
#pragma unroll
            for (int l = 0; l < 4; l++) acc[i][j][l] = 0.f;

    const int arow = lane & 15;
    const int akh = lane >> 4;
    const int brow8 = lane & 7;
    const int bkh = (lane >> 3) & 1;
    const int bni8 = (lane >> 4) & 1;

    for (int i = 0; i < nchunk; i++) {
        if (i + 2 < nchunk) {
            LOAD_STAGE((i + 2) % 3, (i + 2) * 32)
            asm volatile("cp.async.wait_group 2;" ::: "memory");
        } else if (i + 1 < nchunk) {
            asm volatile("cp.async.wait_group 1;" ::: "memory");
        } else {
            asm volatile("cp.async.wait_group 0;" ::: "memory");
        }
        __syncthreads();

        const uint32_t sb = sbase + (i % 3) * GSTAGE;
#pragma unroll
        for (int ks = 0; ks < 2; ks++) {
            uint32_t ah[4][4], al[4][4], bh[4][4], bl[4][4];
#pragma unroll
            for (int mi = 0; mi < 4; mi++) {
                uint32_t off = swz((uint32_t)((wm * 64 + mi * 16 + arow) * 64 + ks * 32 + akh * 16));
                ldx4(ah[mi], sb + off);
                ldx4(al[mi], sb + 8192 + off);
            }
#pragma unroll
            for (int nj = 0; nj < 4; nj++) {
                int r = wn * 64 + nj * 16 + bni8 * 8 + brow8;
                uint32_t off = swz((uint32_t)(r * 64 + ks * 32 + bkh * 16));
                ldx4(bh[nj], sb + 16384 + off);
                ldx4(bl[nj], sb + 32768 + off);
            }
#pragma unroll
            for (int mi = 0; mi < 4; mi++)
#pragma unroll
                for (int nj = 0; nj < 4; nj++) {
                    mma_bf16(acc[mi][2 * nj], ah[mi], &bh[nj][0]);
                    mma_bf16(acc[mi][2 * nj], ah[mi], &bl[nj][0]);
                    mma_bf16(acc[mi][2 * nj], al[mi], &bh[nj][0]);
                    mma_bf16(acc[mi][2 * nj + 1], ah[mi], &bh[nj][2]);
                    mma_bf16(acc[mi][2 * nj + 1], ah[mi], &bl[nj][2]);
                    mma_bf16(acc[mi][2 * nj + 1], al[mi], &bh[nj][2]);
                }
        }
        __syncthreads();
    }

    // Epilogue
#pragma unroll
    for (int mi = 0; mi < 4; mi++) {
        int r0 = bm + wm * 64 + mi * 16 + (lane >> 2);
#pragma unroll
        for (int ni = 0; ni < 8; ni++) {
            int col = bn + wn * 64 + ni * 8 + (lane & 3) * 2;
            float b0 = bias[col], b1 = bias[col + 1];
            float x0 = acc[mi][ni][0] + b0, x1 = acc[mi][ni][1] + b1;
            float x2 = acc[mi][ni][2] + b0, x3 = acc[mi][ni][3] + b1;
            if (C) {
                *(float2*)(C + (size_t)r0 * Nd + col) = make_float2(x0, x1);
                *(float2*)(C + (size_t)(r0 + 8) * Nd + col) = make_float2(x2, x3);
            }
            if (OutH) {
                __nv_bfloat162 lo0, lo1;
                __nv_bfloat162 h0 = split_hi2(x0, x1, lo0);
                __nv_bfloat162 h1 = split_hi2(x2, x3, lo1);
                *(__nv_bfloat162*)(OutH + (size_t)r0 * Nd + col) = h0;
                *(__nv_bfloat162*)(OutL + (size_t)r0 * Nd + col) = lo0;
                *(__nv_bfloat162*)(OutH + (size_t)(r0 + 8) * Nd + col) = h1;
                *(__nv_bfloat162*)(OutL + (size_t)(r0 + 8) * Nd + col) = lo1;
            }
        }
    }
#undef LOAD_STAGE
}

// ---------------------------------------------------------------------------
// fp32 -> (bf16 hi, bf16 lo) split
// ---------------------------------------------------------------------------
__global__ __launch_bounds__(256) void split_bf16(
    const float4* __restrict__ src, __nv_bfloat162* __restrict__ hi,
    __nv_bfloat162* __restrict__ lo, int n4)
{
    int i = blockIdx.x * 256 + threadIdx.x;
    if (i >= n4) return;
    float4 v = src[i];
    __nv_bfloat162 l0, l1;
    __nv_bfloat162 h0 = split_hi2(v.x, v.y, l0);
    __nv_bfloat162 h1 = split_hi2(v.z, v.w, l1);
    hi[2 * i] = h0; hi[2 * i + 1] = h1;
    lo[2 * i] = l0; lo[2 * i + 1] = l1;
}

// ---------------------------------------------------------------------------
// Fused RMSNorm + interleaved RoPE -> bf16 hi/lo splits.
// ---------------------------------------------------------------------------
__global__ __launch_bounds__(256) void rmsnorm_rope_split(
    const float* __restrict__ h, const float* __restrict__ w,
    const float* __restrict__ cosb, const float* __restrict__ sinb,
    __nv_bfloat16* __restrict__ outh, __nv_bfloat16* __restrict__ outl)
{
    const int row = blockIdx.x;
    const int t = row & (T_ - 1);
    const float* hr = h + (size_t)row * D_;

    float ss = 0.f;
    for (int i = threadIdx.x; i < D_; i += 256) { float v = hr[i]; ss += v * v; }
#pragma unroll
    for (int o = 16; o > 0; o >>= 1) ss += __shfl_xor_sync(0xffffffffu, ss, o);
    __shared__ float red[8];
    __shared__ float s_inv;
    if ((threadIdx.x & 31) == 0) red[threadIdx.x >> 5] = ss;
    __syncthreads();
    if (threadIdx.x == 0) {
        float s = 0.f;
        for (int i = 0; i < 8; i++) s += red[i];
        s_inv = rsqrtf(s * (1.0f / D_) + 1e-6f);
    }
    __syncthreads();
    const float inv = s_inv;
    const float* ct = cosb + (size_t)t * D_;
    const float* st = sinb + (size_t)t * D_;
    __nv_bfloat162* oh2 = (__nv_bfloat162*)(outh + (size_t)row * D_);
    __nv_bfloat162* ol2 = (__nv_bfloat162*)(outl + (size_t)row * D_);
    for (int i = threadIdx.x; i < D_ / 2; i += 256) {
        int i2 = i * 2;
        float e = hr[i2] * inv * w[i2];
        float o = hr[i2 + 1] * inv * w[i2 + 1];
        float v0 = e * ct[i2]     - o * st[i2];
        float v1 = o * ct[i2 + 1] + e * st[i2 + 1];
        __nv_bfloat162 lo;
        oh2[i] = split_hi2(v0, v1, lo);
        ol2[i] = lo;
    }
}

// ---------------------------------------------------------------------------
// bf16-split mma.sync flash attention (non-causal); output as bf16 hi/lo.
// BM=64 (4 warps x 16 rows), BN=64 per iter, Dh=128. grid=(T/64,H,B), 128 thr.
// ---------------------------------------------------------------------------
#define FA_STAGE 65536

__global__ __launch_bounds__(128, 1) void flash_attn_mma(
    const __nv_bfloat16* __restrict__ Qh, const __nv_bfloat16* __restrict__ Ql,
    const __nv_bfloat16* __restrict__ Kh, const __nv_bfloat16* __restrict__ Kl,
    const __nv_bfloat16* __restrict__ Vh, const __nv_bfloat16* __restrict__ Vl,
    __nv_bfloat16* __restrict__ Oh, __nv_bfloat16* __restrict__ Ol)
{
    extern __shared__ __align__(1024) unsigned char smem[];
    const int tid = threadIdx.x;
    const int wid = tid >> 5, lane = tid & 31;
    const int b = blockIdx.z, h = blockIdx.y;
    const int q0 = blockIdx.x * 64;
    const uint32_t sbase = smem_u32(smem);
    const size_t rowbase = ((size_t)b * T_) * D_ + h * DH_;

#define LOADKV(it_, stg)                                                         \
    {                                                                            \
        uint32_t sb_ = sbase + (stg) * FA_STAGE;                                 \
        size_t base_ = rowbase + (size_t)((it_) * 64) * D_;                      \
        for (int t = tid; t < 1024; t += 128) {                                  \
            int r_ = t >> 4, c_ = t & 15;                                        \
            uint32_t ph_ = r_ * 256 + ((c_ ^ (r_ & 7)) << 4);                    \
            size_t g_ = base_ + (size_t)r_ * D_ + c_ * 8;                        \
            cpa16(sb_ + ph_,          Kh + g_);                                  \
            cpa16(sb_ + 16384 + ph_,  Kl + g_);                                  \
            cpa16(sb_ + 32768 + ph_,  Vh + g_);                                  \
            cpa16(sb_ + 49152 + ph_,  Vl + g_);                                  \
        }                                                                        \
        asm volatile("cp.async.commit_group;" ::: "memory");                     \
    }

    for (int t = tid; t < 1024; t += 128) {
        int r = t >> 4, c = t & 15;
        uint32_t ph = r * 256 + ((c ^ (r & 7)) << 4);
        size_t g = rowbase + (size_t)(q0 + r) * D_ + c * 8;
        cpa16(sbase + ph, Qh + g);
        cpa16(sbase + 16384 + ph, Ql + g);
    }
    asm volatile("cp.async.commit_group;" ::: "memory");
    asm volatile("cp.async.wait_group 0;" ::: "memory");
    __syncthreads();

    uint32_t qh[8][4], ql[8][4];
    {
        int r = wid * 16 + (lane & 15);
        int khalf = lane >> 4;
#pragma unroll
        for (int kk = 0; kk < 8; kk++) {
            int chunk = kk * 2 + khalf;
            uint32_t ph = r * 256 + ((chunk ^ (r & 7)) << 4);
            ldx4(qh[kk], sbase + ph);
            ldx4(ql[kk], sbase + 16384 + ph);
        }
    }
    __syncthreads();

    float o[16][4];
#pragma unroll
    for (int i = 0; i < 16; i++)
#pragma unroll
        for (int j = 0; j < 4; j++) o[i][j] = 0.f;
    float m0 = -1e30f, m1 = -1e30f, l0 = 0.f, l1 = 0.f;

    LOADKV(0, 0)
    LOADKV(1, 1)

    const float scale = 0.08838834764831845f;
    const int NIT = T_ / 64;

    for (int it = 0; it < NIT; it++) {
        if (it < NIT - 1) { asm volatile("cp.async.wait_group 1;" ::: "memory"); }
        else              { asm volatile("cp.async.wait_group 0;" ::: "memory"); }
        __syncthreads();
        const uint32_t sb = sbase + (it & 1) * FA_STAGE;

        float s[8][4];
#pragma unroll
        for (int n = 0; n < 8; n++)
#pragma unroll
            for (int j = 0; j < 4; j++) s[n][j] = 0.f;

        const int krow_lo = lane & 7;
        const int kkh = ((lane & 15) >> 3) & 1;
#pragma unroll
        for (int kk = 0; kk < 8; kk++) {
#pragma unroll
            for (int n = 0; n < 8; n++) {
                int r = n * 8 + krow_lo;
                int chunk = kk * 2 + kkh;
                uint32_t ph = r * 256 + ((chunk ^ (r & 7)) << 4);
                uint32_t bh[2], bl[2];
                ldx2(bh, sb + ph);
                ldx2(bl, sb + 16384 + ph);
                mma_bf16(s[n], qh[kk], bh);
                mma_bf16(s[n], qh[kk], bl);
                mma_bf16(s[n], ql[kk], bh);
            }
        }

#pragma unroll
        for (int n = 0; n < 8; n++)
#pragma unroll
            for (int j = 0; j < 4; j++) s[n][j] *= scale;

        float cm0 = -1e30f, cm1 = -1e30f;
#pragma unroll
        for (int n = 0; n < 8; n++) {
            cm0 = fmaxf(cm0, fmaxf(s[n][0], s[n][1]));
            cm1 = fmaxf(cm1, fmaxf(s[n][2], s[n][3]));
        }
        cm0 = fmaxf(cm0, __shfl_xor_sync(0xffffffffu, cm0, 1));
        cm0 = fmaxf(cm0, __shfl_xor_sync(0xffffffffu, cm0, 2));
        cm1 = fmaxf(cm1, __shfl_xor_sync(0xffffffffu, cm1, 1));
        cm1 = fmaxf(cm1, __shfl_xor_sync(0xffffffffu, cm1, 2));
        float mn0 = fmaxf(m0, cm0), mn1 = fmaxf(m1, cm1);
        float a0 = __expf(m0 - mn0), a1 = __expf(m1 - mn1);
        float sum0 = 0.f, sum1 = 0.f;
#pragma unroll
        for (int n = 0; n < 8; n++) {
            s[n][0] = __expf(s[n][0] - mn0);
            s[n][1] = __expf(s[n][1] - mn0);
            s[n][2] = __expf(s[n][2] - mn1);
            s[n][3] = __expf(s[n][3] - mn1);
            sum0 += s[n][0] + s[n][1];
            sum1 += s[n][2] + s[n][3];
        }
        sum0 += __shfl_xor_sync(0xffffffffu, sum0, 1);
        sum0 += __shfl_xor_sync(0xffffffffu, sum0, 2);
        sum1 += __shfl_xor_sync(0xffffffffu, sum1, 1);
        sum1 += __shfl_xor_sync(0xffffffffu, sum1, 2);
        l0 = l0 * a0 + sum0;
        l1 = l1 * a1 + sum1;
        m0 = mn0; m1 = mn1;
#pragma unroll
        for (int ni = 0; ni < 16; ni++) {
            o[ni][0] *= a0; o[ni][1] *= a0;
            o[ni][2] *= a1; o[ni][3] *= a1;
        }

        const int vrow = lane & 15;
#pragma unroll
        for (int j = 0; j < 4; j++) {
            uint32_t pa[4], pb[4];
#pragma unroll
            for (int half = 0; half < 2; half++) {
                float x0 = s[2 * j + half][0], x1 = s[2 * j + half][1];
                float x2 = s[2 * j + half][2], x3 = s[2 * j + half][3];
                __nv_bfloat16 h0 = __float2bfloat16(x0), h1 = __float2bfloat16(x1);
                __nv_bfloat16 h2 = __float2bfloat16(x2), h3 = __float2bfloat16(x3);
                pa[2 * half]     = pk(h0, h1);
                pa[2 * half + 1] = pk(h2, h3);
                pb[2 * half]     = pk(__float2bfloat16(x0 - __bfloat162float(h0)),
                                      __float2bfloat16(x1 - __bfloat162float(h1)));
                pb[2 * half + 1] = pk(__float2bfloat16(x2 - __bfloat162float(h2)),
                                      __float2bfloat16(x3 - __bfloat162float(h3)));
            }
            int r = j * 16 + vrow;
#pragma unroll
            for (int ni = 0; ni < 16; ni++) {
                uint32_t ph = r * 256 + ((ni ^ (r & 7)) << 4);
                uint32_t vh[2], vl[2];
                ldx2t(vh, sb + 32768 + ph);
                ldx2t(vl, sb + 49152 + ph);
                mma_bf16(o[ni], pa, vh);
                mma_bf16(o[ni], pa, vl);
                mma_bf16(o[ni], pb, vh);
            }
        }
        __syncthreads();
        if (it + 2 < NIT) { LOADKV(it + 2, it & 1) }
    }

    // ---- store as bf16 hi/lo split ----
    float i0 = 1.f / l0, i1 = 1.f / l1;
    int r_lo = q0 + wid * 16 + (lane >> 2);
#pragma unroll
    for (int ni = 0; ni < 16; ni++) {
        int col = ni * 8 + (lane & 3) * 2;
        size_t idx0 = rowbase + (size_t)r_lo * D_ + col;
        size_t idx1 = rowbase + (size_t)(r_lo + 8) * D_ + col;
        __nv_bfloat162 lo0, lo1;
        __nv_bfloat162 h0 = split_hi2(o[ni][0] * i0, o[ni][1] * i0, lo0);
        __nv_bfloat162 h1 = split_hi2(o[ni][2] * i1, o[ni][3] * i1, lo1);
        *(__nv_bfloat162*)(Oh + idx0) = h0;
        *(__nv_bfloat162*)(Ol + idx0) = lo0;
        *(__nv_bfloat162*)(Oh + idx1) = h1;
        *(__nv_bfloat162*)(Ol + idx1) = lo1;
    }
#undef LOADKV
}

// ---------------------------------------------------------------------------
// Launch
// ---------------------------------------------------------------------------
extern "C" void kernel_launch(void* const* d_in, const int* in_sizes, int n_in,
                              void* d_out, int out_size)
{
    const float* x    = (const float*)d_in[0];
    const float* cosb = (const float*)d_in[1];
    const float* sinb = (const float*)d_in[2];
    const float* Wq   = (const float*)d_in[3];
    const float* bq   = (const float*)d_in[4];
    const float* Wk   = (const float*)d_in[5];
    const float* bk   = (const float*)d_in[6];
    const float* Wv   = (const float*)d_in[7];
    const float* bv   = (const float*)d_in[8];
    const float* qnw  = (const float*)d_in[9];
    const float* knw  = (const float*)d_in[10];
    const float* Wo   = (const float*)d_in[11];
    const float* bo   = (const float*)d_in[12];
    float* out = (float*)d_out;

    float *qp, *kp;
    cudaGetSymbolAddress((void**)&qp, g_q);
    cudaGetSymbolAddress((void**)&kp, g_k);
    __nv_bfloat16 *xh, *xl, *oh, *ol, *qhp, *qlp, *khp, *klp, *vhp, *vlp;
    __nv_bfloat16 *wqh, *wql, *wkh, *wkl, *wvh, *wvl, *woh, *wol;
    cudaGetSymbolAddress((void**)&xh, g_xh);   cudaGetSymbolAddress((void**)&xl, g_xl);
    cudaGetSymbolAddress((void**)&oh, g_oh);   cudaGetSymbolAddress((void**)&ol, g_ol);
    cudaGetSymbolAddress((void**)&qhp, g_qh);  cudaGetSymbolAddress((void**)&qlp, g_ql);
    cudaGetSymbolAddress((void**)&khp, g_kh);  cudaGetSymbolAddress((void**)&klp, g_kl);
    cudaGetSymbolAddress((void**)&vhp, g_vh);  cudaGetSymbolAddress((void**)&vlp, g_vl);
    cudaGetSymbolAddress((void**)&wqh, g_wqh); cudaGetSymbolAddress((void**)&wql, g_wql);
    cudaGetSymbolAddress((void**)&wkh, g_wkh); cudaGetSymbolAddress((void**)&wkl, g_wkl);
    cudaGetSymbolAddress((void**)&wvh, g_wvh); cudaGetSymbolAddress((void**)&wvl, g_wvl);
    cudaGetSymbolAddress((void**)&woh, g_woh); cudaGetSymbolAddress((void**)&wol, g_wol);

    const int nx4 = M_ * D_ / 4;
    const int nw4 = D_ * D_ / 4;
    split_bf16<<<nx4 / 256, 256>>>((const float4*)x,  (__nv_bfloat162*)xh,  (__nv_bfloat162*)xl,  nx4);
    split_bf16<<<nw4 / 256, 256>>>((const float4*)Wq, (__nv_bfloat162*)wqh, (__nv_bfloat162*)wql, nw4);
    split_bf16<<<nw4 / 256, 256>>>((const float4*)Wk, (__nv_bfloat162*)wkh, (__nv_bfloat162*)wkl, nw4);
    split_bf16<<<nw4 / 256, 256>>>((const float4*)Wv, (__nv_bfloat162*)wvh, (__nv_bfloat162*)wvl, nw4);
    split_bf16<<<nw4 / 256, 256>>>((const float4*)Wo, (__nv_bfloat162*)woh, (__nv_bfloat162*)wol, nw4);

    cudaFuncSetAttribute(gemm_mma_split, cudaFuncAttributeMaxDynamicSharedMemorySize, GEMM_SMEM);
    dim3 ggrid(D_ / 256, M_ / 128);   // (8, 32)
    gemm_mma_split<<<ggrid, 256, GEMM_SMEM>>>(xh, xl, wqh, wql, bq, qp, nullptr, nullptr, M_, D_, D_);
    gemm_mma_split<<<ggrid, 256, GEMM_SMEM>>>(xh, xl, wkh, wkl, bk, kp, nullptr, nullptr, M_, D_, D_);
    gemm_mma_split<<<ggrid, 256, GEMM_SMEM>>>(xh, xl, wvh, wvl, bv, nullptr, vhp, vlp, M_, D_, D_);

    rmsnorm_rope_split<<<M_, 256>>>(qp, qnw, cosb, sinb, qhp, qlp);
    rmsnorm_rope_split<<<M_, 256>>>(kp, knw, cosb, sinb, khp, klp);

    cudaFuncSetAttribute(flash_attn_mma, cudaFuncAttributeMaxDynamicSharedMemorySize, 2 * FA_STAGE);
    flash_attn_mma<<<dim3(T_ / 64, H_, B_), 128, 2 * FA_STAGE>>>(qhp, qlp, khp, klp, vhp, vlp, oh, ol);

    gemm_mma_split<<<ggrid, 256, GEMM_SMEM>>>(oh, ol, woh, wol, bo, out, nullptr, nullptr, M_, D_, D_);
}